// round 15
// baseline (speedup 1.0000x reference)
#include <cuda_runtime.h>

#define HH 256
#define WW 256
#define KTOP 10
#define RADIUS 0.015f
#define RR2 (RADIUS * RADIUS)
#define EPSD 1e-4f
#define NP 20000

// 8x4 pixel tiles; each tile processed by a PAIR of warps (front/back half)
#define TSHX 3
#define TSHY 2
#define TGX (WW >> TSHX)      // 32 tiles in x
#define TGY (HH >> TSHY)      // 64 tiles in y
#define NTILES (TGX * TGY)    // 2048
#define CAP 128

typedef unsigned long long u64;
typedef unsigned int u32;

// ---------------- scratch (no allocations allowed) ----------------
__device__ int    g_count[NTILES];          // zero-init; re-zeroed by k_render
__device__ float4 g_bin[NTILES * CAP];      // {x_ndc, y_ndc, z, idx-as-float}

// -------------------------------------------------------------------
// Fused projection + tile binning (unchanged from R14 passing version).
__global__ void __launch_bounds__(256) k_bin(const float* __restrict__ pts,
                                             const float* __restrict__ Rm,
                                             const float* __restrict__ Tv,
                                             const float* __restrict__ focal,
                                             const float* __restrict__ pp) {
    int p = blockIdx.x * blockDim.x + threadIdx.x;
    if (p >= NP) return;
    float px = pts[3 * p + 0];
    float py = pts[3 * p + 1];
    float pz = pts[3 * p + 2];
    float cx = fmaf(px, __ldg(Rm + 0), fmaf(py, __ldg(Rm + 3), fmaf(pz, __ldg(Rm + 6), __ldg(Tv + 0))));
    float cy = fmaf(px, __ldg(Rm + 1), fmaf(py, __ldg(Rm + 4), fmaf(pz, __ldg(Rm + 7), __ldg(Tv + 1))));
    float cz = fmaf(px, __ldg(Rm + 2), fmaf(py, __ldg(Rm + 5), fmaf(pz, __ldg(Rm + 8), __ldg(Tv + 2))));
    if (cz <= 0.01f) return;
    float iz = 1.0f / cz;
    float xn = fmaf(__ldg(focal + 0) * cx, iz, __ldg(pp + 0));
    float yn = fmaf(__ldg(focal + 1) * cy, iz, __ldg(pp + 1));

    float wlo = (1.f - (xn + RADIUS)) * (WW * 0.5f) - 0.5f;
    float whi = (1.f - (xn - RADIUS)) * (WW * 0.5f) - 0.5f;
    int wmin = (int)floorf(wlo);
    int wmax = (int)ceilf(whi);
    float hlo = (1.f - (yn + RADIUS)) * (HH * 0.5f) - 0.5f;
    float hhi = (1.f - (yn - RADIUS)) * (HH * 0.5f) - 0.5f;
    int hmin = (int)floorf(hlo);
    int hmax = (int)ceilf(hhi);
    if (wmax < 0 || wmin > WW - 1 || hmax < 0 || hmin > HH - 1) return;
    wmin = max(wmin, 0); wmax = min(wmax, WW - 1);
    hmin = max(hmin, 0); hmax = min(hmax, HH - 1);
    int tx0 = wmin >> TSHX, tx1 = wmax >> TSHX;   // <=2 in x
    int ty0 = hmin >> TSHY, ty1 = hmax >> TSHY;   // <=3 in y

    bool bx = (tx1 != tx0);
    bool by1 = (ty0 + 1 <= ty1);
    bool by2 = (ty0 + 2 <= ty1);
    int r0 = ty0 * TGX, r1 = (ty0 + 1) * TGX, r2 = (ty0 + 2) * TGX;

    int pa = atomicAdd(&g_count[r0 + tx0], 1);
    int pb = bx         ? atomicAdd(&g_count[r0 + tx1], 1) : CAP;
    int pc = by1        ? atomicAdd(&g_count[r1 + tx0], 1) : CAP;
    int pd = (by1 && bx)? atomicAdd(&g_count[r1 + tx1], 1) : CAP;
    int pe = by2        ? atomicAdd(&g_count[r2 + tx0], 1) : CAP;
    int pf = (by2 && bx)? atomicAdd(&g_count[r2 + tx1], 1) : CAP;

    float4 e = make_float4(xn, yn, cz, __int_as_float(p));
    if (pa < CAP) g_bin[(r0 + tx0) * CAP + pa] = e;
    if (pb < CAP) g_bin[(r0 + tx1) * CAP + pb] = e;
    if (pc < CAP) g_bin[(r1 + tx0) * CAP + pc] = e;
    if (pd < CAP) g_bin[(r1 + tx1) * CAP + pd] = e;
    if (pe < CAP) g_bin[(r2 + tx0) * CAP + pe] = e;
    if (pf < CAP) g_bin[(r2 + tx1) * CAP + pf] = e;
}

// -------------------------------------------------------------------
__device__ __forceinline__ u64 shfl_xor_u64(u64 v, int m) {
    u32 lo = (u32)v, hi = (u32)(v >> 32);
    lo = __shfl_xor_sync(0xffffffffu, lo, m);
    hi = __shfl_xor_sync(0xffffffffu, hi, m);
    return ((u64)hi << 32) | lo;
}

// In-register warp bitonic sort of 128 u64 keys, ascending. Keys unique.
__device__ __forceinline__ void bitonic_warp4(u64* V, int lane) {
#pragma unroll
    for (int ksz = 2; ksz <= 128; ksz <<= 1) {
#pragma unroll
        for (int jsz = ksz >> 1; jsz > 0; jsz >>= 1) {
            if (jsz >= 32) {
                int j32 = jsz >> 5;
#pragma unroll
                for (int k = 0; k < 4; k++) {
                    if ((k & j32) == 0) {
                        int kb = k | j32;
                        bool up = (((k * 32) & ksz) == 0);
                        u64 a = V[k], b = V[kb];
                        if ((a > b) == up) { V[k] = b; V[kb] = a; }
                    }
                }
            } else {
#pragma unroll
                for (int k = 0; k < 4; k++) {
                    u64 p = shfl_xor_u64(V[k], jsz);
                    bool up = (((k * 32 + lane) & ksz) == 0);
                    bool lower = ((lane & jsz) == 0);
                    u64 mn = (V[k] < p) ? V[k] : p;
                    u64 mx = (V[k] < p) ? p : V[k];
                    V[k] = (lower == up) ? mn : mx;
                }
            }
        }
    }
}

// -------------------------------------------------------------------
// Block = 128 thr = 4 warps = 2 tiles. Per tile: front warp composites
// sorted[0,h), back warp composites sorted[h,n) into prefix-records, then
// front folds <= (KTOP - cntF) records. Exact reference order preserved.
__global__ void __launch_bounds__(128) k_render(const float* __restrict__ feats,
                                                float* __restrict__ out) {
    int tid = threadIdx.x;
    int wid = tid >> 5, lane = tid & 31;
    int pair = wid >> 1;          // tile within block (0/1)
    int role = wid & 1;           // 0 = front, 1 = back
    int tile = blockIdx.x * 2 + pair;
    int txi = tile & (TGX - 1), tyi = tile >> 5;
    int w = (txi << TSHX) + (lane & 7);
    int h = (tyi << TSHY) + (lane >> 3);
    int pix = h * WW + w;
    float xs = 1.f - (2.f * w + 1.f) * (1.f / WW);
    float ys = 1.f - (2.f * h + 1.f) * (1.f / HH);

    cudaGridDependencySynchronize();   // PDL: wait for k_bin

    int n = min(g_count[tile], CAP);
    if (role == 0 && lane == 0 && n) g_count[tile] = 0;   // re-arm

    const float4* bin = g_bin + tile * CAP;

    __shared__ float4 s_sh[2][CAP];          // payload, load order
    __shared__ float4 s_sf[2][CAP];          // feature rgb, load order
    __shared__ u64    s_sk[2][CAP];          // keys, load order
    __shared__ float4 s_she[2][CAP];         // payload, sorted order
    __shared__ float4 s_sfe[2][CAP];         // features, sorted order
    __shared__ float4 s_rec[2][KTOP][32];    // back hit: {cB*r, cB*g, cB*b, w}
    __shared__ float  s_rz[2][KTOP][32];     // back hit: w*z
    __shared__ int    s_rn[2][32];           // back hit count per pixel
    float4* SH = s_sh[pair];
    float4* SF = s_sf[pair];
    u64*    SK = s_sk[pair];
    float4* SHE = s_she[pair];
    float4* SFE = s_sfe[pair];

    // stage: front warp j in [0,64), back warp j in [64,128)
#pragma unroll
    for (int k = 0; k < 2; k++) {
        int j = role * 64 + k * 32 + lane;
        u64 key = ~0ull;
        if (j < n) {
            float4 e = bin[j];
            SH[j] = e;
            int idx = __float_as_int(e.w);
            key = ((u64)__float_as_uint(e.z) << 23) | ((u64)(u32)idx << 8) | (u32)j;
            const float* f = feats + 3 * idx;
            SF[j] = make_float4(f[0], f[1], f[2], 0.f);
        }
        SK[j] = key;
    }
    __syncthreads();                          // staging visible to both warps

    // both warps load all keys and run the full sort (duplicated, independent)
    u64 V[4];
#pragma unroll
    for (int k = 0; k < 4; k++) V[k] = SK[k * 32 + lane];
    bitonic_warp4(V, lane);

    int hs = (n + 1) >> 1;                    // split point
    // permute own half into sorted-order arrays
#pragma unroll
    for (int k = 0; k < 4; k++) {
        int i = k * 32 + lane;
        bool mine = role ? (i >= hs && i < n) : (i < hs);
        if (mine) {
            unsigned slot = (unsigned)(V[k] & 0xFF);
            SHE[i] = SH[slot];
            SFE[i] = SF[slot];
        }
    }
    __syncwarp();

    int cnt = 0;
    float T = 1.f, wsum = 0.f, wz = 0.f;
    float r = 0.f, g = 0.f, b = 0.f;

    if (role == 0) {
        // front composite over sorted [0, hs)
#pragma unroll 4
        for (int j = 0; j < hs; j++) {
            float4 e = SHE[j];
            float dx = xs - e.x;
            float dy = ys - e.y;
            float d2 = fmaf(dx, dx, dy * dy);
            if (d2 < RR2 && cnt < KTOP) {
                float wgt = 1.f - d2 * (1.f / RR2);
                float4 f = SFE[j];
                float cw = wgt * T;
                r = fmaf(cw, f.x, r);
                g = fmaf(cw, f.y, g);
                b = fmaf(cw, f.z, b);
                wsum += wgt;
                wz = fmaf(wgt, e.z, wz);
                T *= (1.f - wgt);
                cnt++;
            }
        }
    } else {
        // back composite over sorted [hs, n): record prefix-composited hits
        float Tb = 1.f;
#pragma unroll 4
        for (int j = hs; j < n; j++) {
            float4 e = SHE[j];
            float dx = xs - e.x;
            float dy = ys - e.y;
            float d2 = fmaf(dx, dx, dy * dy);
            if (d2 < RR2 && cnt < KTOP) {
                float wgt = 1.f - d2 * (1.f / RR2);
                float4 f = SFE[j];
                float cB = wgt * Tb;
                s_rec[pair][cnt][lane] = make_float4(cB * f.x, cB * f.y, cB * f.z, wgt);
                s_rz[pair][cnt][lane] = wgt * e.z;
                Tb *= (1.f - wgt);
                cnt++;
            }
        }
        s_rn[pair][lane] = cnt;
    }

    __syncthreads();                          // back records visible to front

    if (role == 0) {
        // fold back-half records: first (KTOP - cnt) of them
        int nb = s_rn[pair][lane];
        int kk = min(KTOP - cnt, nb);
        float tp = 1.f;
        for (int i = 0; i < kk; i++) {
            float4 rec = s_rec[pair][i][lane];
            float rz = s_rz[pair][i][lane];
            r = fmaf(T, rec.x, r);            // T_F * cB * rgb
            g = fmaf(T, rec.y, g);
            b = fmaf(T, rec.z, b);
            wsum += rec.w;
            wz += rz;
            tp *= (1.f - rec.w);
        }
        T *= tp;

        out[pix * 3 + 0] = fminf(fmaxf(r, 0.f), 1.f);
        out[pix * 3 + 1] = fminf(fmaxf(g, 0.f), 1.f);
        out[pix * 3 + 2] = fminf(fmaxf(b, 0.f), 1.f);
        out[HH * WW * 3 + pix] = 1.f - T;                    // mask
        out[HH * WW * 4 + pix] = wz / fmaxf(wsum, EPSD);     // depth
    }
}

extern "C" void kernel_launch(void* const* d_in, const int* in_sizes, int n_in,
                              void* d_out, int out_size) {
    const float* points    = (const float*)d_in[0];
    const float* features  = (const float*)d_in[1];
    const float* Rm        = (const float*)d_in[2];
    const float* Tv        = (const float*)d_in[3];
    const float* focal     = (const float*)d_in[4];
    const float* principal = (const float*)d_in[5];
    float* out = (float*)d_out;

    k_bin<<<(NP + 255) / 256, 256>>>(points, Rm, Tv, focal, principal);

    // PDL: overlap k_render launch/prologue with k_bin tail
    cudaLaunchConfig_t cfg = {};
    cfg.gridDim  = dim3(NTILES / 2, 1, 1);
    cfg.blockDim = dim3(128, 1, 1);
    cudaLaunchAttribute attrs[1];
    attrs[0].id = cudaLaunchAttributeProgrammaticStreamSerialization;
    attrs[0].val.programmaticStreamSerializationAllowed = 1;
    cfg.attrs = attrs;
    cfg.numAttrs = 1;
    cudaLaunchKernelEx(&cfg, k_render, (const float*)features, (float*)out);
}

// round 16
// speedup vs baseline: 1.1593x; 1.1593x over previous
#include <cuda_runtime.h>

#define HH 256
#define WW 256
#define KTOP 10
#define RADIUS 0.015f
#define RR2 (RADIUS * RADIUS)
#define EPSD 1e-4f
#define NP 20000

// 8x4 pixel tiles; each tile processed by a PAIR of warps (front/back half)
#define TSHX 3
#define TSHY 2
#define TGX (WW >> TSHX)      // 32 tiles in x
#define TGY (HH >> TSHY)      // 64 tiles in y
#define NTILES (TGX * TGY)    // 2048
#define CAP 128

typedef unsigned long long u64;
typedef unsigned int u32;

// ---------------- scratch (no allocations allowed) ----------------
__device__ int    g_count[NTILES];          // zero-init; re-zeroed by k_render
__device__ float4 g_bin[NTILES * CAP];      // {x_ndc, y_ndc, z, idx-as-float}

// -------------------------------------------------------------------
// Fused projection + tile binning (unchanged, measured good).
__global__ void __launch_bounds__(256) k_bin(const float* __restrict__ pts,
                                             const float* __restrict__ Rm,
                                             const float* __restrict__ Tv,
                                             const float* __restrict__ focal,
                                             const float* __restrict__ pp) {
    int p = blockIdx.x * blockDim.x + threadIdx.x;
    if (p >= NP) return;
    float px = pts[3 * p + 0];
    float py = pts[3 * p + 1];
    float pz = pts[3 * p + 2];
    float cx = fmaf(px, __ldg(Rm + 0), fmaf(py, __ldg(Rm + 3), fmaf(pz, __ldg(Rm + 6), __ldg(Tv + 0))));
    float cy = fmaf(px, __ldg(Rm + 1), fmaf(py, __ldg(Rm + 4), fmaf(pz, __ldg(Rm + 7), __ldg(Tv + 1))));
    float cz = fmaf(px, __ldg(Rm + 2), fmaf(py, __ldg(Rm + 5), fmaf(pz, __ldg(Rm + 8), __ldg(Tv + 2))));
    if (cz <= 0.01f) return;
    float iz = 1.0f / cz;
    float xn = fmaf(__ldg(focal + 0) * cx, iz, __ldg(pp + 0));
    float yn = fmaf(__ldg(focal + 1) * cy, iz, __ldg(pp + 1));

    float wlo = (1.f - (xn + RADIUS)) * (WW * 0.5f) - 0.5f;
    float whi = (1.f - (xn - RADIUS)) * (WW * 0.5f) - 0.5f;
    int wmin = (int)floorf(wlo);
    int wmax = (int)ceilf(whi);
    float hlo = (1.f - (yn + RADIUS)) * (HH * 0.5f) - 0.5f;
    float hhi = (1.f - (yn - RADIUS)) * (HH * 0.5f) - 0.5f;
    int hmin = (int)floorf(hlo);
    int hmax = (int)ceilf(hhi);
    if (wmax < 0 || wmin > WW - 1 || hmax < 0 || hmin > HH - 1) return;
    wmin = max(wmin, 0); wmax = min(wmax, WW - 1);
    hmin = max(hmin, 0); hmax = min(hmax, HH - 1);
    int tx0 = wmin >> TSHX, tx1 = wmax >> TSHX;   // <=2 in x
    int ty0 = hmin >> TSHY, ty1 = hmax >> TSHY;   // <=3 in y

    bool bx = (tx1 != tx0);
    bool by1 = (ty0 + 1 <= ty1);
    bool by2 = (ty0 + 2 <= ty1);
    int r0 = ty0 * TGX, r1 = (ty0 + 1) * TGX, r2 = (ty0 + 2) * TGX;

    int pa = atomicAdd(&g_count[r0 + tx0], 1);
    int pb = bx         ? atomicAdd(&g_count[r0 + tx1], 1) : CAP;
    int pc = by1        ? atomicAdd(&g_count[r1 + tx0], 1) : CAP;
    int pd = (by1 && bx)? atomicAdd(&g_count[r1 + tx1], 1) : CAP;
    int pe = by2        ? atomicAdd(&g_count[r2 + tx0], 1) : CAP;
    int pf = (by2 && bx)? atomicAdd(&g_count[r2 + tx1], 1) : CAP;

    float4 e = make_float4(xn, yn, cz, __int_as_float(p));
    if (pa < CAP) g_bin[(r0 + tx0) * CAP + pa] = e;
    if (pb < CAP) g_bin[(r0 + tx1) * CAP + pb] = e;
    if (pc < CAP) g_bin[(r1 + tx0) * CAP + pc] = e;
    if (pd < CAP) g_bin[(r1 + tx1) * CAP + pd] = e;
    if (pe < CAP) g_bin[(r2 + tx0) * CAP + pe] = e;
    if (pf < CAP) g_bin[(r2 + tx1) * CAP + pf] = e;
}

// -------------------------------------------------------------------
__device__ __forceinline__ u64 shfl_xor_u64(u64 v, int m) {
    u32 lo = (u32)v, hi = (u32)(v >> 32);
    lo = __shfl_xor_sync(0xffffffffu, lo, m);
    hi = __shfl_xor_sync(0xffffffffu, hi, m);
    return ((u64)hi << 32) | lo;
}

// In-register warp bitonic sort of NK*32 u64 keys, ascending. Keys unique.
template <int NK>
__device__ __forceinline__ void bitonic_warp(u64* V, int lane) {
    const int M = NK * 32;
#pragma unroll
    for (int ksz = 2; ksz <= M; ksz <<= 1) {
#pragma unroll
        for (int jsz = ksz >> 1; jsz > 0; jsz >>= 1) {
            if (jsz >= 32) {
                int j32 = jsz >> 5;
#pragma unroll
                for (int k = 0; k < NK; k++) {
                    if ((k & j32) == 0) {
                        int kb = k | j32;
                        bool up = (((k * 32) & ksz) == 0);
                        u64 a = V[k], b = V[kb];
                        if ((a > b) == up) { V[k] = b; V[kb] = a; }
                    }
                }
            } else {
#pragma unroll
                for (int k = 0; k < NK; k++) {
                    u64 p = shfl_xor_u64(V[k], jsz);
                    bool up = (((k * 32 + lane) & ksz) == 0);
                    bool lower = ((lane & jsz) == 0);
                    u64 mn = (V[k] < p) ? V[k] : p;
                    u64 mx = (V[k] < p) ? p : V[k];
                    V[k] = (lower == up) ? mn : mx;
                }
            }
        }
    }
}

// -------------------------------------------------------------------
// Block = 128 thr = 4 warps = 2 tiles. Per tile: front warp composites
// sorted[0,hs), back warp composites sorted[hs,n) into prefix-records,
// then front folds <= (KTOP - cntF) records. Exact reference order.
// Sort width adaptive: n<=64 -> NK=2 (the ~99.8% case), else NK=4.
__global__ void __launch_bounds__(128) k_render(const float* __restrict__ feats,
                                                float* __restrict__ out) {
    int tid = threadIdx.x;
    int wid = tid >> 5, lane = tid & 31;
    int pair = wid >> 1;          // tile within block (0/1)
    int role = wid & 1;           // 0 = front, 1 = back
    int tile = blockIdx.x * 2 + pair;
    int txi = tile & (TGX - 1), tyi = tile >> 5;
    int w = (txi << TSHX) + (lane & 7);
    int h = (tyi << TSHY) + (lane >> 3);
    int pix = h * WW + w;
    float xs = 1.f - (2.f * w + 1.f) * (1.f / WW);
    float ys = 1.f - (2.f * h + 1.f) * (1.f / HH);

    cudaGridDependencySynchronize();   // PDL: wait for k_bin

    int n = min(g_count[tile], CAP);
    const float4* bin = g_bin + tile * CAP;

    __shared__ float4 s_sh[2][CAP];          // payload, load order
    __shared__ float4 s_sf[2][CAP];          // feature rgb, load order
    __shared__ u64    s_sk[2][CAP];          // keys, load order
    __shared__ float4 s_she[2][CAP];         // payload, sorted order
    __shared__ float4 s_sfe[2][CAP];         // features, sorted order
    __shared__ float4 s_rec[2][KTOP][32];    // back hit: {cB*r, cB*g, cB*b, w}
    __shared__ float  s_rz[2][KTOP][32];     // back hit: w*z
    __shared__ int    s_rn[2][32];           // back hit count per pixel
    float4* SH = s_sh[pair];
    float4* SF = s_sf[pair];
    u64*    SK = s_sk[pair];
    float4* SHE = s_she[pair];
    float4* SFE = s_sfe[pair];

    // stage: front warp j in [0,64), back warp j in [64,128)
#pragma unroll
    for (int k = 0; k < 2; k++) {
        int j = role * 64 + k * 32 + lane;
        u64 key = ~0ull;
        if (j < n) {
            float4 e = bin[j];
            SH[j] = e;
            int idx = __float_as_int(e.w);
            key = ((u64)__float_as_uint(e.z) << 23) | ((u64)(u32)idx << 8) | (u32)j;
            const float* f = feats + 3 * idx;
            SF[j] = make_float4(f[0], f[1], f[2], 0.f);
        }
        SK[j] = key;
    }
    __syncthreads();                          // staging visible; n reads done
    if (role == 0 && lane == 0 && n) g_count[tile] = 0;   // safe re-arm

    // both warps sort (duplicated, independent). Adaptive width.
    u64 V[4];
    int nk = (n <= 64) ? 2 : 4;
#pragma unroll
    for (int k = 0; k < 4; k++) V[k] = (k < nk) ? SK[k * 32 + lane] : ~0ull;
    if (nk == 2) bitonic_warp<2>(V, lane);
    else         bitonic_warp<4>(V, lane);

    int hs = (n + 1) >> 1;                    // split point
    // permute own half into sorted-order arrays
#pragma unroll
    for (int k = 0; k < 4; k++) {
        int i = k * 32 + lane;
        if (k < nk) {
            bool mine = role ? (i >= hs && i < n) : (i < hs);
            if (mine) {
                unsigned slot = (unsigned)(V[k] & 0xFF);
                SHE[i] = SH[slot];
                SFE[i] = SF[slot];
            }
        }
    }
    __syncwarp();

    int cnt = 0;
    float T = 1.f, wsum = 0.f, wz = 0.f;
    float r = 0.f, g = 0.f, b = 0.f;

    if (role == 0) {
        // front composite over sorted [0, hs)
#pragma unroll 4
        for (int j = 0; j < hs; j++) {
            float4 e = SHE[j];
            float dx = xs - e.x;
            float dy = ys - e.y;
            float d2 = fmaf(dx, dx, dy * dy);
            if (d2 < RR2 && cnt < KTOP) {
                float wgt = 1.f - d2 * (1.f / RR2);
                float4 f = SFE[j];
                float cw = wgt * T;
                r = fmaf(cw, f.x, r);
                g = fmaf(cw, f.y, g);
                b = fmaf(cw, f.z, b);
                wsum += wgt;
                wz = fmaf(wgt, e.z, wz);
                T *= (1.f - wgt);
                cnt++;
            }
        }
    } else {
        // back composite over sorted [hs, n): record prefix-composited hits
        float Tb = 1.f;
#pragma unroll 4
        for (int j = hs; j < n; j++) {
            float4 e = SHE[j];
            float dx = xs - e.x;
            float dy = ys - e.y;
            float d2 = fmaf(dx, dx, dy * dy);
            if (d2 < RR2 && cnt < KTOP) {
                float wgt = 1.f - d2 * (1.f / RR2);
                float4 f = SFE[j];
                float cB = wgt * Tb;
                s_rec[pair][cnt][lane] = make_float4(cB * f.x, cB * f.y, cB * f.z, wgt);
                s_rz[pair][cnt][lane] = wgt * e.z;
                Tb *= (1.f - wgt);
                cnt++;
            }
        }
        s_rn[pair][lane] = cnt;
    }

    __syncthreads();                          // back records visible to front

    if (role == 0) {
        // fold back-half records: first (KTOP - cnt) of them
        int nb = s_rn[pair][lane];
        int kk = min(KTOP - cnt, nb);
        float tp = 1.f;
        for (int i = 0; i < kk; i++) {
            float4 rec = s_rec[pair][i][lane];
            float rz = s_rz[pair][i][lane];
            r = fmaf(T, rec.x, r);            // T_F * cB * rgb
            g = fmaf(T, rec.y, g);
            b = fmaf(T, rec.z, b);
            wsum += rec.w;
            wz += rz;
            tp *= (1.f - rec.w);
        }
        T *= tp;

        out[pix * 3 + 0] = fminf(fmaxf(r, 0.f), 1.f);
        out[pix * 3 + 1] = fminf(fmaxf(g, 0.f), 1.f);
        out[pix * 3 + 2] = fminf(fmaxf(b, 0.f), 1.f);
        out[HH * WW * 3 + pix] = 1.f - T;                    // mask
        out[HH * WW * 4 + pix] = wz / fmaxf(wsum, EPSD);     // depth
    }
}

extern "C" void kernel_launch(void* const* d_in, const int* in_sizes, int n_in,
                              void* d_out, int out_size) {
    const float* points    = (const float*)d_in[0];
    const float* features  = (const float*)d_in[1];
    const float* Rm        = (const float*)d_in[2];
    const float* Tv        = (const float*)d_in[3];
    const float* focal     = (const float*)d_in[4];
    const float* principal = (const float*)d_in[5];
    float* out = (float*)d_out;

    k_bin<<<(NP + 255) / 256, 256>>>(points, Rm, Tv, focal, principal);

    // PDL: overlap k_render launch/prologue with k_bin tail
    cudaLaunchConfig_t cfg = {};
    cfg.gridDim  = dim3(NTILES / 2, 1, 1);
    cfg.blockDim = dim3(128, 1, 1);
    cudaLaunchAttribute attrs[1];
    attrs[0].id = cudaLaunchAttributeProgrammaticStreamSerialization;
    attrs[0].val.programmaticStreamSerializationAllowed = 1;
    cfg.attrs = attrs;
    cfg.numAttrs = 1;
    cudaLaunchKernelEx(&cfg, k_render, (const float*)features, (float*)out);
}

// round 17
// speedup vs baseline: 1.2883x; 1.1113x over previous
#include <cuda_runtime.h>

#define HH 256
#define WW 256
#define KTOP 10
#define RADIUS 0.015f
#define RR2 (RADIUS * RADIUS)
#define EPSD 1e-4f
#define NP 20000

// 8x4 pixel tiles; each tile processed by a PAIR of warps (front/back half)
#define TSHX 3
#define TSHY 2
#define TGX (WW >> TSHX)      // 32 tiles in x
#define TGY (HH >> TSHY)      // 64 tiles in y
#define NTILES (TGX * TGY)    // 2048
#define CAP 128

typedef unsigned long long u64;
typedef unsigned int u32;

// ---------------- scratch (no allocations allowed) ----------------
__device__ int    g_count[NTILES];          // zero-init; re-zeroed by k_render
__device__ float4 g_bin[NTILES * CAP];      // {x_ndc, y_ndc, z, idx-as-float}

// -------------------------------------------------------------------
// Fused projection + tile binning (unchanged, measured good).
__global__ void __launch_bounds__(256) k_bin(const float* __restrict__ pts,
                                             const float* __restrict__ Rm,
                                             const float* __restrict__ Tv,
                                             const float* __restrict__ focal,
                                             const float* __restrict__ pp) {
    int p = blockIdx.x * blockDim.x + threadIdx.x;
    if (p >= NP) return;
    float px = pts[3 * p + 0];
    float py = pts[3 * p + 1];
    float pz = pts[3 * p + 2];
    float cx = fmaf(px, __ldg(Rm + 0), fmaf(py, __ldg(Rm + 3), fmaf(pz, __ldg(Rm + 6), __ldg(Tv + 0))));
    float cy = fmaf(px, __ldg(Rm + 1), fmaf(py, __ldg(Rm + 4), fmaf(pz, __ldg(Rm + 7), __ldg(Tv + 1))));
    float cz = fmaf(px, __ldg(Rm + 2), fmaf(py, __ldg(Rm + 5), fmaf(pz, __ldg(Rm + 8), __ldg(Tv + 2))));
    if (cz <= 0.01f) return;
    float iz = 1.0f / cz;
    float xn = fmaf(__ldg(focal + 0) * cx, iz, __ldg(pp + 0));
    float yn = fmaf(__ldg(focal + 1) * cy, iz, __ldg(pp + 1));

    float wlo = (1.f - (xn + RADIUS)) * (WW * 0.5f) - 0.5f;
    float whi = (1.f - (xn - RADIUS)) * (WW * 0.5f) - 0.5f;
    int wmin = (int)floorf(wlo);
    int wmax = (int)ceilf(whi);
    float hlo = (1.f - (yn + RADIUS)) * (HH * 0.5f) - 0.5f;
    float hhi = (1.f - (yn - RADIUS)) * (HH * 0.5f) - 0.5f;
    int hmin = (int)floorf(hlo);
    int hmax = (int)ceilf(hhi);
    if (wmax < 0 || wmin > WW - 1 || hmax < 0 || hmin > HH - 1) return;
    wmin = max(wmin, 0); wmax = min(wmax, WW - 1);
    hmin = max(hmin, 0); hmax = min(hmax, HH - 1);
    int tx0 = wmin >> TSHX, tx1 = wmax >> TSHX;   // <=2 in x
    int ty0 = hmin >> TSHY, ty1 = hmax >> TSHY;   // <=3 in y

    bool bx = (tx1 != tx0);
    bool by1 = (ty0 + 1 <= ty1);
    bool by2 = (ty0 + 2 <= ty1);
    int r0 = ty0 * TGX, r1 = (ty0 + 1) * TGX, r2 = (ty0 + 2) * TGX;

    int pa = atomicAdd(&g_count[r0 + tx0], 1);
    int pb = bx         ? atomicAdd(&g_count[r0 + tx1], 1) : CAP;
    int pc = by1        ? atomicAdd(&g_count[r1 + tx0], 1) : CAP;
    int pd = (by1 && bx)? atomicAdd(&g_count[r1 + tx1], 1) : CAP;
    int pe = by2        ? atomicAdd(&g_count[r2 + tx0], 1) : CAP;
    int pf = (by2 && bx)? atomicAdd(&g_count[r2 + tx1], 1) : CAP;

    float4 e = make_float4(xn, yn, cz, __int_as_float(p));
    if (pa < CAP) g_bin[(r0 + tx0) * CAP + pa] = e;
    if (pb < CAP) g_bin[(r0 + tx1) * CAP + pb] = e;
    if (pc < CAP) g_bin[(r1 + tx0) * CAP + pc] = e;
    if (pd < CAP) g_bin[(r1 + tx1) * CAP + pd] = e;
    if (pe < CAP) g_bin[(r2 + tx0) * CAP + pe] = e;
    if (pf < CAP) g_bin[(r2 + tx1) * CAP + pf] = e;
}

// -------------------------------------------------------------------
__device__ __forceinline__ u64 shfl_xor_u64(u64 v, int m) {
    u32 lo = (u32)v, hi = (u32)(v >> 32);
    lo = __shfl_xor_sync(0xffffffffu, lo, m);
    hi = __shfl_xor_sync(0xffffffffu, hi, m);
    return ((u64)hi << 32) | lo;
}

// In-register warp bitonic sort of NK*32 u64 keys, ascending. Keys unique.
template <int NK>
__device__ __forceinline__ void bitonic_warp(u64* V, int lane) {
    const int M = NK * 32;
#pragma unroll
    for (int ksz = 2; ksz <= M; ksz <<= 1) {
#pragma unroll
        for (int jsz = ksz >> 1; jsz > 0; jsz >>= 1) {
            if (jsz >= 32) {
                int j32 = jsz >> 5;
#pragma unroll
                for (int k = 0; k < NK; k++) {
                    if ((k & j32) == 0) {
                        int kb = k | j32;
                        bool up = (((k * 32) & ksz) == 0);
                        u64 a = V[k], b = V[kb];
                        if ((a > b) == up) { V[k] = b; V[kb] = a; }
                    }
                }
            } else {
#pragma unroll
                for (int k = 0; k < NK; k++) {
                    u64 p = shfl_xor_u64(V[k], jsz);
                    bool up = (((k * 32 + lane) & ksz) == 0);
                    bool lower = ((lane & jsz) == 0);
                    u64 mn = (V[k] < p) ? V[k] : p;
                    u64 mx = (V[k] < p) ? p : V[k];
                    V[k] = (lower == up) ? mn : mx;
                }
            }
        }
    }
}

// -------------------------------------------------------------------
// Block = 128 thr = 4 warps = 2 tiles. Single-sorter split:
//   front warp: sort + permute WHOLE list, composite sorted[0,hs)
//   back warp:  stage its half, wait, composite sorted[hs,n) into records
//   front folds <= (KTOP - cntF) records. Exact reference order.
__global__ void __launch_bounds__(128) k_render(const float* __restrict__ feats,
                                                float* __restrict__ out) {
    int tid = threadIdx.x;
    int wid = tid >> 5, lane = tid & 31;
    int pair = wid >> 1;          // tile within block (0/1)
    int role = wid & 1;           // 0 = front (sorter), 1 = back
    int tile = blockIdx.x * 2 + pair;
    int txi = tile & (TGX - 1), tyi = tile >> 5;
    int w = (txi << TSHX) + (lane & 7);
    int h = (tyi << TSHY) + (lane >> 3);
    int pix = h * WW + w;
    float xs = 1.f - (2.f * w + 1.f) * (1.f / WW);
    float ys = 1.f - (2.f * h + 1.f) * (1.f / HH);

    cudaGridDependencySynchronize();   // PDL: wait for k_bin

    int n = min(g_count[tile], CAP);
    const float4* bin = g_bin + tile * CAP;

    __shared__ float4 s_sh[2][CAP];          // payload, load order
    __shared__ float4 s_sf[2][CAP];          // feature rgb, load order
    __shared__ u64    s_sk[2][CAP];          // keys, load order
    __shared__ float4 s_she[2][CAP];         // payload, sorted order
    __shared__ float4 s_sfe[2][CAP];         // features, sorted order
    __shared__ float4 s_rec[2][KTOP][32];    // back hit: {cB*r, cB*g, cB*b, w}
    __shared__ float  s_rz[2][KTOP][32];     // back hit: w*z
    __shared__ int    s_rn[2][32];           // back hit count per pixel
    float4* SH = s_sh[pair];
    float4* SF = s_sf[pair];
    u64*    SK = s_sk[pair];
    float4* SHE = s_she[pair];
    float4* SFE = s_sfe[pair];

    // stage: front warp j in [0,64), back warp j in [64,128)
#pragma unroll
    for (int k = 0; k < 2; k++) {
        int j = role * 64 + k * 32 + lane;
        u64 key = ~0ull;
        if (j < n) {
            float4 e = bin[j];
            SH[j] = e;
            int idx = __float_as_int(e.w);
            key = ((u64)__float_as_uint(e.z) << 23) | ((u64)(u32)idx << 8) | (u32)j;
            const float* f = feats + 3 * idx;
            SF[j] = make_float4(f[0], f[1], f[2], 0.f);
        }
        SK[j] = key;
    }
    __syncthreads();                          // staging visible; n reads done
    if (role == 0 && lane == 0 && n) g_count[tile] = 0;   // safe re-arm

    int hs = (n + 1) >> 1;                    // split point

    // ONLY the front warp sorts and permutes the whole list
    if (role == 0) {
        u64 V[4];
        int nk = (n <= 64) ? 2 : 4;
#pragma unroll
        for (int k = 0; k < 4; k++) V[k] = (k < nk) ? SK[k * 32 + lane] : ~0ull;
        if (nk == 2) bitonic_warp<2>(V, lane);
        else         bitonic_warp<4>(V, lane);
#pragma unroll
        for (int k = 0; k < 4; k++) {
            int i = k * 32 + lane;
            if (k < nk && i < n) {
                unsigned slot = (unsigned)(V[k] & 0xFF);
                SHE[i] = SH[slot];
                SFE[i] = SF[slot];
            }
        }
    }
    __syncthreads();                          // sorted arrays visible to back

    int cnt = 0;
    float T = 1.f, wsum = 0.f, wz = 0.f;
    float r = 0.f, g = 0.f, b = 0.f;

    if (role == 0) {
        // front composite over sorted [0, hs)
#pragma unroll 4
        for (int j = 0; j < hs; j++) {
            float4 e = SHE[j];
            float dx = xs - e.x;
            float dy = ys - e.y;
            float d2 = fmaf(dx, dx, dy * dy);
            if (d2 < RR2 && cnt < KTOP) {
                float wgt = 1.f - d2 * (1.f / RR2);
                float4 f = SFE[j];
                float cw = wgt * T;
                r = fmaf(cw, f.x, r);
                g = fmaf(cw, f.y, g);
                b = fmaf(cw, f.z, b);
                wsum += wgt;
                wz = fmaf(wgt, e.z, wz);
                T *= (1.f - wgt);
                cnt++;
            }
        }
    } else {
        // back composite over sorted [hs, n): record prefix-composited hits
        float Tb = 1.f;
#pragma unroll 4
        for (int j = hs; j < n; j++) {
            float4 e = SHE[j];
            float dx = xs - e.x;
            float dy = ys - e.y;
            float d2 = fmaf(dx, dx, dy * dy);
            if (d2 < RR2 && cnt < KTOP) {
                float wgt = 1.f - d2 * (1.f / RR2);
                float4 f = SFE[j];
                float cB = wgt * Tb;
                s_rec[pair][cnt][lane] = make_float4(cB * f.x, cB * f.y, cB * f.z, wgt);
                s_rz[pair][cnt][lane] = wgt * e.z;
                Tb *= (1.f - wgt);
                cnt++;
            }
        }
        s_rn[pair][lane] = cnt;
    }

    __syncthreads();                          // back records visible to front

    if (role == 0) {
        // fold back-half records: first (KTOP - cnt) of them
        int nb = s_rn[pair][lane];
        int kk = min(KTOP - cnt, nb);
        float tp = 1.f;
        for (int i = 0; i < kk; i++) {
            float4 rec = s_rec[pair][i][lane];
            float rz = s_rz[pair][i][lane];
            r = fmaf(T, rec.x, r);            // T_F * cB * rgb
            g = fmaf(T, rec.y, g);
            b = fmaf(T, rec.z, b);
            wsum += rec.w;
            wz += rz;
            tp *= (1.f - rec.w);
        }
        T *= tp;

        out[pix * 3 + 0] = fminf(fmaxf(r, 0.f), 1.f);
        out[pix * 3 + 1] = fminf(fmaxf(g, 0.f), 1.f);
        out[pix * 3 + 2] = fminf(fmaxf(b, 0.f), 1.f);
        out[HH * WW * 3 + pix] = 1.f - T;                    // mask
        out[HH * WW * 4 + pix] = wz / fmaxf(wsum, EPSD);     // depth
    }
}

extern "C" void kernel_launch(void* const* d_in, const int* in_sizes, int n_in,
                              void* d_out, int out_size) {
    const float* points    = (const float*)d_in[0];
    const float* features  = (const float*)d_in[1];
    const float* Rm        = (const float*)d_in[2];
    const float* Tv        = (const float*)d_in[3];
    const float* focal     = (const float*)d_in[4];
    const float* principal = (const float*)d_in[5];
    float* out = (float*)d_out;

    k_bin<<<(NP + 255) / 256, 256>>>(points, Rm, Tv, focal, principal);

    // PDL: overlap k_render launch/prologue with k_bin tail
    cudaLaunchConfig_t cfg = {};
    cfg.gridDim  = dim3(NTILES / 2, 1, 1);
    cfg.blockDim = dim3(128, 1, 1);
    cudaLaunchAttribute attrs[1];
    attrs[0].id = cudaLaunchAttributeProgrammaticStreamSerialization;
    attrs[0].val.programmaticStreamSerializationAllowed = 1;
    cfg.attrs = attrs;
    cfg.numAttrs = 1;
    cudaLaunchKernelEx(&cfg, k_render, (const float*)features, (float*)out);
}